// round 11
// baseline (speedup 1.0000x reference)
#include <cuda_runtime.h>

// ============================================================================
// TorusConv3D via FFT diagonalization (round 11).
// Round-11: round-10 fused persistent kernel with the grid barrier FIXED.
// Round-10's barrier polled with atomicAdd (same-address L2 atomic RMW ->
// ~32cyc serialized per poller -> ~5us/barrier with 260 CTAs). Now: arrival
// via one atomicAdd, polling via volatile LOADs (+nanosleep backoff), release
// via volatile store; release/acquire ordering via __threadfence. CTAs that
// don't consume the next stage's data arrive without spinning.
// ============================================================================

typedef unsigned long long ull;

// Packed spectra: g_Xp[k*2048 + b*32 + j], g_Wp[k*2048 + f*32 + j],
//                 g_Z [k*2048 + b*32 + fp]
__device__ ull g_Xp[512 * 2048];
__device__ ull g_Wp[512 * 2048];
__device__ ull g_Z[512 * 2048];

// Barrier state. gen is monotonic across graph replays; cnt resets each use.
__device__ unsigned g_cnt[2];
__device__ volatile unsigned g_gen[2];

#define GRID_CTAS 260

// Software grid barrier. All GRID_CTAS CTAs must call (resident-wave safe:
// launch_bounds(512,2) x 148 SMs = 296 slots >= 260). If do_wait is false the
// CTA arrives but does not spin (safe when it reads none of the protected data).
__device__ __forceinline__ void grid_barrier(int which, bool do_wait) {
    __syncthreads();
    if (threadIdx.x == 0) {
        const unsigned my = g_gen[which];   // volatile read BEFORE arriving
        __threadfence();                    // release this stage's writes
        const unsigned old = atomicAdd(&g_cnt[which], 1u);
        if (old == GRID_CTAS - 1) {
            g_cnt[which] = 0;
            __threadfence();
            g_gen[which] = my + 1;          // volatile release store
        } else if (do_wait) {
            while (g_gen[which] == my) __nanosleep(64);  // volatile load spin
            __threadfence();                // acquire
        }
    }
    __syncthreads();
}

// ---------------------------------------------------------------------------
// Packed f32x2 primitives. A complex value is (re, im) = (lo, hi) of an ull.
// ---------------------------------------------------------------------------
__device__ __forceinline__ ull pk(float lo, float hi) {
    ull r;
    asm("mov.b64 %0, {%1, %2};" : "=l"(r) : "f"(lo), "f"(hi));
    return r;
}
__device__ __forceinline__ void upk(ull v, float& lo, float& hi) {
    asm("mov.b64 {%0, %1}, %2;" : "=f"(lo), "=f"(hi) : "l"(v));
}
__device__ __forceinline__ ull add2(ull a, ull b) {
    ull d;
    asm("add.rn.f32x2 %0, %1, %2;" : "=l"(d) : "l"(a), "l"(b));
    return d;
}
__device__ __forceinline__ ull mul2(ull a, ull b) {
    ull d;
    asm("mul.rn.f32x2 %0, %1, %2;" : "=l"(d) : "l"(a), "l"(b));
    return d;
}
__device__ __forceinline__ ull fma2(ull a, ull b, ull c) {
    ull d;
    asm("fma.rn.f32x2 %0, %1, %2, %3;" : "=l"(d) : "l"(a), "l"(b), "l"(c));
    return d;
}
__device__ __forceinline__ ull sub2(ull a, ull b) {
    return fma2(b, 0xBF800000BF800000ULL, a);  // a + (-1)*b
}
__device__ __forceinline__ float negf(float x) {
    return __uint_as_float(__float_as_uint(x) ^ 0x80000000u);
}
template <int INV>
__device__ __forceinline__ ull mi(ull a) {  // *(-i) fwd, *(+i) inv
    float x, y;
    upk(a, x, y);
    return INV ? pk(negf(y), x) : pk(y, negf(x));
}

#define R2R2 0x3F3504F33F3504F3ULL  // (sqrt(0.5), sqrt(0.5))

template <int INV>
__device__ __forceinline__ void fft8p(ull* v) {
    ull t0 = add2(v[0], v[4]), t1 = sub2(v[0], v[4]);
    ull t2 = add2(v[2], v[6]), t3 = sub2(v[2], v[6]);
    ull t4 = add2(v[1], v[5]), t5 = sub2(v[1], v[5]);
    ull t6 = add2(v[3], v[7]), t7 = sub2(v[3], v[7]);
    ull a0 = add2(t0, t2), a1 = sub2(t0, t2);
    ull m3 = mi<INV>(t3);
    ull a2 = add2(t1, m3), a3 = sub2(t1, m3);
    ull b0 = add2(t4, t6), b1 = sub2(t4, t6);
    ull m7 = mi<INV>(t7);
    ull b2 = add2(t5, m7), b3 = sub2(t5, m7);
    ull mb1 = mi<INV>(b1);
    ull w1v = mul2(add2(b2, mi<INV>(b2)), R2R2);
    ull w3v = mi<INV>(mul2(add2(b3, mi<INV>(b3)), R2R2));
    v[0] = add2(a0, b0); v[4] = sub2(a0, b0);
    v[2] = add2(a1, mb1); v[6] = sub2(a1, mb1);
    v[1] = add2(a2, w1v); v[5] = sub2(a2, w1v);
    v[3] = add2(a3, w3v); v[7] = sub2(a3, w3v);
}

// ---------------------------------------------------------------------------
// Fused persistent kernel. smem union: FFT V[512*16] ull (64 KB) /
// pointwise As[64*65]+Bs[64*65] float2 (66.56 KB).
// ---------------------------------------------------------------------------
__global__ void __launch_bounds__(512, 2)
torus_fused(const float* __restrict__ inputs, const float* __restrict__ kern,
            const float* __restrict__ bias, float* __restrict__ out) {
    extern __shared__ ull SM[];
    const int blk = blockIdx.x;
    const int tid = threadIdx.x;

    // ======================= Stage A: forward FFT =======================
    if (blk < 256) {
        ull* V = SM;
        int t_ = blk;
        const float* in;
        ull* outp;
        long rowStride, sStride;
        if (t_ < 128) { in = inputs; outp = g_Xp; rowStride = 32768; sStride = 64; }
        else          { t_ -= 128; in = kern; outp = g_Wp; rowStride = 64; sStride = 4096; }
        const int row = t_ >> 1, j0 = (t_ & 1) * 16;
        const int c = tid & 15, pp = tid >> 4;

        const float* base = in + (long)row * rowStride + 2 * (j0 + c);
        ull buf[8];

#pragma unroll
        for (int m = 0; m < 2; ++m) {  // z-axis + load
            const int t = pp + 32 * m;
#pragma unroll
            for (int z = 0; z < 8; ++z)
                buf[z] = *(const ull*)(base + (long)(8 * t + z) * sStride);
            fft8p<0>(buf);
#pragma unroll
            for (int z = 0; z < 8; ++z) V[(8 * t + z) * 16 + c] = buf[z];
        }
        __syncthreads();
#pragma unroll
        for (int m = 0; m < 2; ++m) {  // y-axis
            const int t = pp + 32 * m;
            const int b0 = ((t >> 3) * 64 + (t & 7)) * 16 + c;
#pragma unroll
            for (int y = 0; y < 8; ++y) buf[y] = V[b0 + y * 128];
            fft8p<0>(buf);
#pragma unroll
            for (int y = 0; y < 8; ++y) V[b0 + y * 128] = buf[y];
        }
        __syncthreads();
        ull* og = outp + row * 32 + j0 + c;
#pragma unroll
        for (int m = 0; m < 2; ++m) {  // x-axis + store
            const int t = pp + 32 * m;
#pragma unroll
            for (int x = 0; x < 8; ++x) buf[x] = V[t * 16 + c + x * 1024];
            fft8p<0>(buf);
#pragma unroll
            for (int x = 0; x < 8; ++x) og[(long)(x * 64 + t) * 2048] = buf[x];
        }
    }

    grid_barrier(0, true);  // everyone consumes spectra in stage B

    // ======================= Stage B: pointwise GEMM =======================
    {
        float2* As = (float2*)SM;            // [c][b], stride 65
        float2* Bs = (float2*)SM + 64 * 65;  // [c][f], stride 65
        const int rank = blk;
        int kx, ky, kz;
        if (rank < 192) {
            kx = 1 + rank / 64; const int r = rank & 63; ky = r >> 3; kz = r & 7;
        } else if (rank < 240) {
            const int r = rank - 192; kx = (r / 24) * 4;
            const int r2 = r % 24; ky = 1 + r2 / 8; kz = r2 & 7;
        } else {
            const int r = rank - 240; kx = (r / 10) * 4;
            const int r2 = r % 10; ky = (r2 / 5) * 4; kz = r2 % 5;
        }
        const int k = (kx << 6) | (ky << 3) | kz;
        const int neg = (((8 - kx) & 7) << 6) | (((8 - ky) & 7) << 3) | ((8 - kz) & 7);

        const float2* xk = (const float2*)g_Xp + (long)k * 2048;
        const float2* xn = (const float2*)g_Xp + (long)neg * 2048;
        const float2* wk = (const float2*)g_Wp + (long)k * 2048;
        const float2* wn = (const float2*)g_Wp + (long)neg * 2048;
        for (int i = tid; i < 2048; i += 512) {
            const int j = i & 31, rowi = i >> 5;
            const int c0 = 2 * j, c1 = 2 * j + 1;
            {
                const float2 Pk = xk[i], Pn = xn[i];
                As[c0 * 65 + rowi] = make_float2(0.5f * (Pk.x + Pn.x), 0.5f * (Pk.y - Pn.y));
                As[c1 * 65 + rowi] = make_float2(0.5f * (Pk.y + Pn.y), 0.5f * (Pn.x - Pk.x));
            }
            {
                const float2 Pk = wk[i], Pn = wn[i];
                Bs[c0 * 65 + rowi] = make_float2(0.5f * (Pk.x + Pn.x), 0.5f * (Pk.y - Pn.y));
                Bs[c1 * 65 + rowi] = make_float2(0.5f * (Pk.y + Pn.y), 0.5f * (Pn.x - Pk.x));
            }
        }
        __syncthreads();

        const int ft = tid & 15;   // f = ft + 16j
        const int bt = tid >> 4;   // b = bt + 32i
        ull acc[2][4];
#pragma unroll
        for (int i = 0; i < 2; ++i)
#pragma unroll
            for (int j = 0; j < 4; ++j) acc[i][j] = 0ULL;

        ull axax[2], nay[2], bxy[4], byx[4];
#pragma unroll 2
        for (int cc = 0; cc < 64; ++cc) {
#pragma unroll
            for (int i = 0; i < 2; ++i) {
                const float2 t = As[cc * 65 + bt + 32 * i];
                axax[i] = pk(t.x, t.x);
                nay[i] = pk(negf(t.y), t.y);
            }
#pragma unroll
            for (int j = 0; j < 4; ++j) {
                const float2 t = Bs[cc * 65 + ft + 16 * j];
                bxy[j] = pk(t.x, t.y);
                byx[j] = pk(t.y, t.x);
            }
#pragma unroll
            for (int i = 0; i < 2; ++i)
#pragma unroll
                for (int j = 0; j < 4; ++j) {
                    acc[i][j] = fma2(axax[i], bxy[j], acc[i][j]);
                    acc[i][j] = fma2(nay[i], byx[j], acc[i][j]);
                }
        }

        float2* zk = (float2*)g_Z + (long)k * 2048;
        float2* zn = (float2*)g_Z + (long)neg * 2048;
        const bool self = (k == neg);
        const bool even = (ft & 1) == 0;
        const int fp0 = ft >> 1;
#pragma unroll
        for (int i = 0; i < 2; ++i)
#pragma unroll
            for (int j = 0; j < 4; ++j) {
                const ull part = __shfl_xor_sync(0xffffffffu, acc[i][j], 1);
                if (even) {
                    float y0x, y0y, y1x, y1y;
                    upk(acc[i][j], y0x, y0y);
                    upk(part, y1x, y1y);
                    const int idx = (bt + 32 * i) * 32 + fp0 + 8 * j;
                    zk[idx] = make_float2(y0x - y1y, y0y + y1x);
                    if (!self) zn[idx] = make_float2(y0x + y1y, y1x - y0y);
                }
            }
    }

    // Only CTAs < 128 consume Z in stage C; others arrive without spinning.
    grid_barrier(1, blk < 128);

    // ======================= Stage C: inverse FFT =======================
    if (blk < 128) {
        ull* V = SM;
        const int b = blk >> 1, fp0 = (blk & 1) * 16;
        const int c = tid & 15, pp = tid >> 4;
        const float2 bv = ((const float2*)bias)[fp0 + c];

        const ull* yg = g_Z + b * 32 + fp0 + c;
        ull buf[8];

#pragma unroll
        for (int m = 0; m < 2; ++m) {  // z-axis + load
            const int t = pp + 32 * m;
#pragma unroll
            for (int z = 0; z < 8; ++z) buf[z] = yg[(long)(8 * t + z) * 2048];
            fft8p<1>(buf);
#pragma unroll
            for (int z = 0; z < 8; ++z) V[(8 * t + z) * 16 + c] = buf[z];
        }
        __syncthreads();
#pragma unroll
        for (int m = 0; m < 2; ++m) {  // y-axis
            const int t = pp + 32 * m;
            const int b0 = ((t >> 3) * 64 + (t & 7)) * 16 + c;
#pragma unroll
            for (int y = 0; y < 8; ++y) buf[y] = V[b0 + y * 128];
            fft8p<1>(buf);
#pragma unroll
            for (int y = 0; y < 8; ++y) V[b0 + y * 128] = buf[y];
        }
        __syncthreads();
        float2* og = (float2*)out + (long)b * 512 * 32 + fp0 + c;
#pragma unroll
        for (int m = 0; m < 2; ++m) {  // x-axis + store
            const int t = pp + 32 * m;
#pragma unroll
            for (int x = 0; x < 8; ++x) buf[x] = V[t * 16 + c + x * 1024];
            fft8p<1>(buf);
#pragma unroll
            for (int x = 0; x < 8; ++x) {
                float re, im;
                upk(buf[x], re, im);
                og[(long)(x * 64 + t) * 32] =
                    make_float2(re * (1.f / 512.f) + bv.x, im * (1.f / 512.f) + bv.y);
            }
        }
    }
}

// ---------------------------------------------------------------------------
extern "C" void kernel_launch(void* const* d_in, const int* in_sizes, int n_in,
                              void* d_out, int out_size) {
    const float* inputs = (const float*)d_in[0];
    const float* kern   = (const float*)d_in[1];
    const float* bias   = (const float*)d_in[2];
    float* out = (float*)d_out;

    const int smemBytes = 2 * 64 * 65 * (int)sizeof(float2);  // 66560 B
    cudaFuncSetAttribute(torus_fused, cudaFuncAttributeMaxDynamicSharedMemorySize, smemBytes);

    torus_fused<<<GRID_CTAS, 512, smemBytes>>>(inputs, kern, bias, out);
}

// round 13
// speedup vs baseline: 1.0234x; 1.0234x over previous
#include <cuda_runtime.h>

// ============================================================================
// TorusConv3D via FFT diagonalization (round 12, resubmitted after infra fail).
// Round-12: TWO kernels, ONE barrier. fwd stays standalone (best measured
// 9.7us, no barrier tax). pointwise+ifft fuse into one persistent kernel
// (260 CTAs x 256 threads, 3/SM resident -> 444 slots >= 260) with a single
// volatile-spin grid barrier (no nanosleep), removing one launch/drain gap.
// Stage bodies identical to round-8's verified versions.
// ============================================================================

typedef unsigned long long ull;

// Packed spectra: g_Xp[k*2048 + b*32 + j], g_Wp[k*2048 + f*32 + j],
//                 g_Z [k*2048 + b*32 + fp]
__device__ ull g_Xp[512 * 2048];
__device__ ull g_Wp[512 * 2048];
__device__ ull g_Z[512 * 2048];

// Barrier state. gen is monotonic across graph replays; cnt resets each use.
__device__ unsigned g_cnt;
__device__ volatile unsigned g_gen;

#define K2_CTAS 260

// ---------------------------------------------------------------------------
// Packed f32x2 primitives. A complex value is (re, im) = (lo, hi) of an ull.
// ---------------------------------------------------------------------------
__device__ __forceinline__ ull pk(float lo, float hi) {
    ull r;
    asm("mov.b64 %0, {%1, %2};" : "=l"(r) : "f"(lo), "f"(hi));
    return r;
}
__device__ __forceinline__ void upk(ull v, float& lo, float& hi) {
    asm("mov.b64 {%0, %1}, %2;" : "=f"(lo), "=f"(hi) : "l"(v));
}
__device__ __forceinline__ ull add2(ull a, ull b) {
    ull d;
    asm("add.rn.f32x2 %0, %1, %2;" : "=l"(d) : "l"(a), "l"(b));
    return d;
}
__device__ __forceinline__ ull mul2(ull a, ull b) {
    ull d;
    asm("mul.rn.f32x2 %0, %1, %2;" : "=l"(d) : "l"(a), "l"(b));
    return d;
}
__device__ __forceinline__ ull fma2(ull a, ull b, ull c) {
    ull d;
    asm("fma.rn.f32x2 %0, %1, %2, %3;" : "=l"(d) : "l"(a), "l"(b), "l"(c));
    return d;
}
__device__ __forceinline__ ull sub2(ull a, ull b) {
    return fma2(b, 0xBF800000BF800000ULL, a);  // a + (-1)*b
}
__device__ __forceinline__ float negf(float x) {
    return __uint_as_float(__float_as_uint(x) ^ 0x80000000u);
}
template <int INV>
__device__ __forceinline__ ull mi(ull a) {  // *(-i) fwd, *(+i) inv
    float x, y;
    upk(a, x, y);
    return INV ? pk(negf(y), x) : pk(y, negf(x));
}

#define R2R2 0x3F3504F33F3504F3ULL  // (sqrt(0.5), sqrt(0.5))

template <int INV>
__device__ __forceinline__ void fft8p(ull* v) {
    ull t0 = add2(v[0], v[4]), t1 = sub2(v[0], v[4]);
    ull t2 = add2(v[2], v[6]), t3 = sub2(v[2], v[6]);
    ull t4 = add2(v[1], v[5]), t5 = sub2(v[1], v[5]);
    ull t6 = add2(v[3], v[7]), t7 = sub2(v[3], v[7]);
    ull a0 = add2(t0, t2), a1 = sub2(t0, t2);
    ull m3 = mi<INV>(t3);
    ull a2 = add2(t1, m3), a3 = sub2(t1, m3);
    ull b0 = add2(t4, t6), b1 = sub2(t4, t6);
    ull m7 = mi<INV>(t7);
    ull b2 = add2(t5, m7), b3 = sub2(t5, m7);
    ull mb1 = mi<INV>(b1);
    ull w1v = mul2(add2(b2, mi<INV>(b2)), R2R2);
    ull w3v = mi<INV>(mul2(add2(b3, mi<INV>(b3)), R2R2));
    v[0] = add2(a0, b0); v[4] = sub2(a0, b0);
    v[2] = add2(a1, mb1); v[6] = sub2(a1, mb1);
    v[1] = add2(a2, w1v); v[5] = sub2(a2, w1v);
    v[3] = add2(a3, w3v); v[7] = sub2(a3, w3v);
}

// ---------------------------------------------------------------------------
// Kernel 1: forward packed FFT, 16-column tiles, 512 threads (round-8 shape).
// Blocks [0,128) -> inputs->Xp, [128,256) -> kernel->Wp.
// ---------------------------------------------------------------------------
__global__ void __launch_bounds__(512)
fft3d_fwd_packed(const float* __restrict__ inA, const float* __restrict__ inB,
                 ull* __restrict__ outA, ull* __restrict__ outB) {
    extern __shared__ ull V[];
    int blk = blockIdx.x;
    const float* in;
    ull* out;
    long rowStride, sStride;
    if (blk < 128) { in = inA; out = outA; rowStride = 32768; sStride = 64; }
    else           { blk -= 128; in = inB; out = outB; rowStride = 64; sStride = 4096; }
    const int row = blk >> 1, j0 = (blk & 1) * 16;
    const int tid = threadIdx.x;
    const int c = tid & 15, pp = tid >> 4;

    const float* base = in + (long)row * rowStride + 2 * (j0 + c);
    ull buf[8];

#pragma unroll
    for (int m = 0; m < 2; ++m) {  // z-axis + load
        const int t = pp + 32 * m;
#pragma unroll
        for (int z = 0; z < 8; ++z)
            buf[z] = *(const ull*)(base + (long)(8 * t + z) * sStride);
        fft8p<0>(buf);
#pragma unroll
        for (int z = 0; z < 8; ++z) V[(8 * t + z) * 16 + c] = buf[z];
    }
    __syncthreads();
#pragma unroll
    for (int m = 0; m < 2; ++m) {  // y-axis
        const int t = pp + 32 * m;
        const int b0 = ((t >> 3) * 64 + (t & 7)) * 16 + c;
#pragma unroll
        for (int y = 0; y < 8; ++y) buf[y] = V[b0 + y * 128];
        fft8p<0>(buf);
#pragma unroll
        for (int y = 0; y < 8; ++y) V[b0 + y * 128] = buf[y];
    }
    __syncthreads();
    ull* og = out + row * 32 + j0 + c;
#pragma unroll
    for (int m = 0; m < 2; ++m) {  // x-axis + store
        const int t = pp + 32 * m;
#pragma unroll
        for (int x = 0; x < 8; ++x) buf[x] = V[t * 16 + c + x * 1024];
        fft8p<0>(buf);
#pragma unroll
        for (int x = 0; x < 8; ++x) og[(long)(x * 64 + t) * 2048] = buf[x];
    }
}

// ---------------------------------------------------------------------------
// Kernel 2: pointwise (260 tasks) + grid barrier + inverse FFT (128 tasks).
// 256 threads, launch_bounds(256,3): 3 CTAs/SM x 148 = 444 slots >= 260, so
// the whole grid is resident wave-1 -> barrier is deadlock-free.
// smem union: pw As[64*65]+Bs[64*65] float2 (66.56 KB) / ifft V[512*16] ull.
// ---------------------------------------------------------------------------
__global__ void __launch_bounds__(256, 3)
pw_ifft_fused(const float* __restrict__ bias, float* __restrict__ out) {
    extern __shared__ ull SM[];
    const int blk = blockIdx.x;
    const int tid = threadIdx.x;

    // ===================== Stage B: pointwise GEMM =====================
    {
        float2* As = (float2*)SM;            // [c][b], stride 65
        float2* Bs = (float2*)SM + 64 * 65;  // [c][f], stride 65
        const int rank = blk;
        int kx, ky, kz;
        if (rank < 192) {
            kx = 1 + rank / 64; const int r = rank & 63; ky = r >> 3; kz = r & 7;
        } else if (rank < 240) {
            const int r = rank - 192; kx = (r / 24) * 4;
            const int r2 = r % 24; ky = 1 + r2 / 8; kz = r2 & 7;
        } else {
            const int r = rank - 240; kx = (r / 10) * 4;
            const int r2 = r % 10; ky = (r2 / 5) * 4; kz = r2 % 5;
        }
        const int k = (kx << 6) | (ky << 3) | kz;
        const int neg = (((8 - kx) & 7) << 6) | (((8 - ky) & 7) << 3) | ((8 - kz) & 7);

        const float2* xk = (const float2*)g_Xp + (long)k * 2048;
        const float2* xn = (const float2*)g_Xp + (long)neg * 2048;
        const float2* wk = (const float2*)g_Wp + (long)k * 2048;
        const float2* wn = (const float2*)g_Wp + (long)neg * 2048;
        for (int i = tid; i < 2048; i += 256) {
            const int j = i & 31, rowi = i >> 5;
            const int c0 = 2 * j, c1 = 2 * j + 1;
            {
                const float2 Pk = xk[i], Pn = xn[i];
                As[c0 * 65 + rowi] = make_float2(0.5f * (Pk.x + Pn.x), 0.5f * (Pk.y - Pn.y));
                As[c1 * 65 + rowi] = make_float2(0.5f * (Pk.y + Pn.y), 0.5f * (Pn.x - Pk.x));
            }
            {
                const float2 Pk = wk[i], Pn = wn[i];
                Bs[c0 * 65 + rowi] = make_float2(0.5f * (Pk.x + Pn.x), 0.5f * (Pk.y - Pn.y));
                Bs[c1 * 65 + rowi] = make_float2(0.5f * (Pk.y + Pn.y), 0.5f * (Pn.x - Pk.x));
            }
        }
        __syncthreads();

        const int ft = tid & 15;
        const int bt = tid >> 4;
        ull acc[4][4];
#pragma unroll
        for (int i = 0; i < 4; ++i)
#pragma unroll
            for (int j = 0; j < 4; ++j) acc[i][j] = 0ULL;

        ull axax[4], nay[4], bxy[4], byx[4];
#pragma unroll 2
        for (int cc = 0; cc < 64; ++cc) {
#pragma unroll
            for (int i = 0; i < 4; ++i) {
                const float2 t = As[cc * 65 + bt + 16 * i];
                axax[i] = pk(t.x, t.x);
                nay[i] = pk(negf(t.y), t.y);
            }
#pragma unroll
            for (int j = 0; j < 4; ++j) {
                const float2 t = Bs[cc * 65 + ft + 16 * j];
                bxy[j] = pk(t.x, t.y);
                byx[j] = pk(t.y, t.x);
            }
#pragma unroll
            for (int i = 0; i < 4; ++i)
#pragma unroll
                for (int j = 0; j < 4; ++j) {
                    acc[i][j] = fma2(axax[i], bxy[j], acc[i][j]);
                    acc[i][j] = fma2(nay[i], byx[j], acc[i][j]);
                }
        }

        float2* zk = (float2*)g_Z + (long)k * 2048;
        float2* zn = (float2*)g_Z + (long)neg * 2048;
        const bool self = (k == neg);
        const bool even = (ft & 1) == 0;
        const int fp0 = ft >> 1;
#pragma unroll
        for (int i = 0; i < 4; ++i)
#pragma unroll
            for (int j = 0; j < 4; ++j) {
                const ull part = __shfl_xor_sync(0xffffffffu, acc[i][j], 1);
                if (even) {
                    float y0x, y0y, y1x, y1y;
                    upk(acc[i][j], y0x, y0y);
                    upk(part, y1x, y1y);
                    const int idx = (bt + 16 * i) * 32 + fp0 + 8 * j;
                    zk[idx] = make_float2(y0x - y1y, y0y + y1x);
                    if (!self) zn[idx] = make_float2(y0x + y1y, y1x - y0y);
                }
            }
    }

    // ===================== Grid barrier (single) =====================
    // CTAs >= 128 arrive and exit (they read no Z); CTAs < 128 wait.
    {
        const bool do_wait = (blk < 128);
        __syncthreads();
        if (threadIdx.x == 0) {
            const unsigned my = g_gen;      // volatile read BEFORE arriving
            __threadfence();                // release stage-B writes
            const unsigned old = atomicAdd(&g_cnt, 1u);
            if (old == K2_CTAS - 1) {
                g_cnt = 0;
                __threadfence();
                g_gen = my + 1;             // volatile release store
            } else if (do_wait) {
                while (g_gen == my) { }     // pure volatile spin (no nanosleep)
                __threadfence();            // acquire
            }
        }
        __syncthreads();
        if (!do_wait) return;
    }

    // ===================== Stage C: inverse FFT =====================
    {
        ull* V = SM;
        const int b = blk >> 1, fp0 = (blk & 1) * 16;
        const int c = tid & 15, pp = tid >> 4;
        const float2 bv = ((const float2*)bias)[fp0 + c];

        const ull* yg = g_Z + b * 32 + fp0 + c;
        ull buf[8];

#pragma unroll
        for (int m = 0; m < 4; ++m) {  // z-axis + load
            const int t = pp + 16 * m;
#pragma unroll
            for (int z = 0; z < 8; ++z) buf[z] = yg[(long)(8 * t + z) * 2048];
            fft8p<1>(buf);
#pragma unroll
            for (int z = 0; z < 8; ++z) V[(8 * t + z) * 16 + c] = buf[z];
        }
        __syncthreads();
#pragma unroll
        for (int m = 0; m < 4; ++m) {  // y-axis
            const int t = pp + 16 * m;
            const int b0 = ((t >> 3) * 64 + (t & 7)) * 16 + c;
#pragma unroll
            for (int y = 0; y < 8; ++y) buf[y] = V[b0 + y * 128];
            fft8p<1>(buf);
#pragma unroll
            for (int y = 0; y < 8; ++y) V[b0 + y * 128] = buf[y];
        }
        __syncthreads();
        float2* og = (float2*)out + (long)b * 512 * 32 + fp0 + c;
#pragma unroll
        for (int m = 0; m < 4; ++m) {  // x-axis + store
            const int t = pp + 16 * m;
#pragma unroll
            for (int x = 0; x < 8; ++x) buf[x] = V[t * 16 + c + x * 1024];
            fft8p<1>(buf);
#pragma unroll
            for (int x = 0; x < 8; ++x) {
                float re, im;
                upk(buf[x], re, im);
                og[(long)(x * 64 + t) * 32] =
                    make_float2(re * (1.f / 512.f) + bv.x, im * (1.f / 512.f) + bv.y);
            }
        }
    }
}

// ---------------------------------------------------------------------------
extern "C" void kernel_launch(void* const* d_in, const int* in_sizes, int n_in,
                              void* d_out, int out_size) {
    const float* inputs = (const float*)d_in[0];
    const float* kern   = (const float*)d_in[1];
    const float* bias   = (const float*)d_in[2];
    float* out = (float*)d_out;

    ull *Xp, *Wp;
    cudaGetSymbolAddress((void**)&Xp, g_Xp);
    cudaGetSymbolAddress((void**)&Wp, g_Wp);

    const int smemFFT = 512 * 16 * (int)sizeof(ull);       // 65536 B
    const int smemK2  = 2 * 64 * 65 * (int)sizeof(float2); // 66560 B
    cudaFuncSetAttribute(fft3d_fwd_packed, cudaFuncAttributeMaxDynamicSharedMemorySize, smemFFT);
    cudaFuncSetAttribute(pw_ifft_fused,    cudaFuncAttributeMaxDynamicSharedMemorySize, smemK2);

    fft3d_fwd_packed<<<256, 512, smemFFT>>>(inputs, kern, Xp, Wp);
    pw_ifft_fused<<<K2_CTAS, 256, smemK2>>>(bias, out);
}

// round 14
// speedup vs baseline: 1.1480x; 1.1217x over previous
#include <cuda_runtime.h>

// ============================================================================
// TorusConv3D via FFT diagonalization (round 14).
// Round-14: back to the plain 3-kernel chain (barrier variants R10/11/13 all
// lost; ncu cold-cache inflation had exaggerated the launch gaps). Pointwise
// inner loop reformulated: accumulate P = sum ax*(bx,by), Q = sum ay*(bx,by)
// so B loads feed fma2 with NO packing movs; fixup Y = (P.lo - Q.hi,
// P.hi + Q.lo) after the loop. ~28% fewer issued instructions in the hot loop.
// ============================================================================

typedef unsigned long long ull;

// Packed spectra: g_Xp[k*2048 + b*32 + j], g_Wp[k*2048 + f*32 + j],
//                 g_Z [k*2048 + b*32 + fp]
__device__ ull g_Xp[512 * 2048];
__device__ ull g_Wp[512 * 2048];
__device__ ull g_Z[512 * 2048];

// ---------------------------------------------------------------------------
// Packed f32x2 primitives. A complex value is (re, im) = (lo, hi) of an ull.
// ---------------------------------------------------------------------------
__device__ __forceinline__ ull pk(float lo, float hi) {
    ull r;
    asm("mov.b64 %0, {%1, %2};" : "=l"(r) : "f"(lo), "f"(hi));
    return r;
}
__device__ __forceinline__ void upk(ull v, float& lo, float& hi) {
    asm("mov.b64 {%0, %1}, %2;" : "=f"(lo), "=f"(hi) : "l"(v));
}
__device__ __forceinline__ ull add2(ull a, ull b) {
    ull d;
    asm("add.rn.f32x2 %0, %1, %2;" : "=l"(d) : "l"(a), "l"(b));
    return d;
}
__device__ __forceinline__ ull mul2(ull a, ull b) {
    ull d;
    asm("mul.rn.f32x2 %0, %1, %2;" : "=l"(d) : "l"(a), "l"(b));
    return d;
}
__device__ __forceinline__ ull fma2(ull a, ull b, ull c) {
    ull d;
    asm("fma.rn.f32x2 %0, %1, %2, %3;" : "=l"(d) : "l"(a), "l"(b), "l"(c));
    return d;
}
__device__ __forceinline__ ull sub2(ull a, ull b) {
    return fma2(b, 0xBF800000BF800000ULL, a);  // a + (-1)*b
}
__device__ __forceinline__ float negf(float x) {
    return __uint_as_float(__float_as_uint(x) ^ 0x80000000u);
}
template <int INV>
__device__ __forceinline__ ull mi(ull a) {  // *(-i) fwd, *(+i) inv
    float x, y;
    upk(a, x, y);
    return INV ? pk(negf(y), x) : pk(y, negf(x));
}

#define R2R2 0x3F3504F33F3504F3ULL  // (sqrt(0.5), sqrt(0.5))

template <int INV>
__device__ __forceinline__ void fft8p(ull* v) {
    ull t0 = add2(v[0], v[4]), t1 = sub2(v[0], v[4]);
    ull t2 = add2(v[2], v[6]), t3 = sub2(v[2], v[6]);
    ull t4 = add2(v[1], v[5]), t5 = sub2(v[1], v[5]);
    ull t6 = add2(v[3], v[7]), t7 = sub2(v[3], v[7]);
    ull a0 = add2(t0, t2), a1 = sub2(t0, t2);
    ull m3 = mi<INV>(t3);
    ull a2 = add2(t1, m3), a3 = sub2(t1, m3);
    ull b0 = add2(t4, t6), b1 = sub2(t4, t6);
    ull m7 = mi<INV>(t7);
    ull b2 = add2(t5, m7), b3 = sub2(t5, m7);
    ull mb1 = mi<INV>(b1);
    ull w1v = mul2(add2(b2, mi<INV>(b2)), R2R2);
    ull w3v = mi<INV>(mul2(add2(b3, mi<INV>(b3)), R2R2));
    v[0] = add2(a0, b0); v[4] = sub2(a0, b0);
    v[2] = add2(a1, mb1); v[6] = sub2(a1, mb1);
    v[1] = add2(a2, w1v); v[5] = sub2(a2, w1v);
    v[3] = add2(a3, w3v); v[7] = sub2(a3, w3v);
}

// ---------------------------------------------------------------------------
// Kernel 1: forward packed FFT, 16-column tiles, 512 threads.
// Blocks [0,128) -> inputs->Xp, [128,256) -> kernel->Wp.
// ---------------------------------------------------------------------------
__global__ void __launch_bounds__(512)
fft3d_fwd_packed(const float* __restrict__ inA, const float* __restrict__ inB,
                 ull* __restrict__ outA, ull* __restrict__ outB) {
    extern __shared__ ull V[];
    int blk = blockIdx.x;
    const float* in;
    ull* out;
    long rowStride, sStride;
    if (blk < 128) { in = inA; out = outA; rowStride = 32768; sStride = 64; }
    else           { blk -= 128; in = inB; out = outB; rowStride = 64; sStride = 4096; }
    const int row = blk >> 1, j0 = (blk & 1) * 16;
    const int tid = threadIdx.x;
    const int c = tid & 15, pp = tid >> 4;

    const float* base = in + (long)row * rowStride + 2 * (j0 + c);
    ull buf[8];

#pragma unroll
    for (int m = 0; m < 2; ++m) {  // z-axis + load
        const int t = pp + 32 * m;
#pragma unroll
        for (int z = 0; z < 8; ++z)
            buf[z] = *(const ull*)(base + (long)(8 * t + z) * sStride);
        fft8p<0>(buf);
#pragma unroll
        for (int z = 0; z < 8; ++z) V[(8 * t + z) * 16 + c] = buf[z];
    }
    __syncthreads();
#pragma unroll
    for (int m = 0; m < 2; ++m) {  // y-axis
        const int t = pp + 32 * m;
        const int b0 = ((t >> 3) * 64 + (t & 7)) * 16 + c;
#pragma unroll
        for (int y = 0; y < 8; ++y) buf[y] = V[b0 + y * 128];
        fft8p<0>(buf);
#pragma unroll
        for (int y = 0; y < 8; ++y) V[b0 + y * 128] = buf[y];
    }
    __syncthreads();
    ull* og = out + row * 32 + j0 + c;
#pragma unroll
    for (int m = 0; m < 2; ++m) {  // x-axis + store
        const int t = pp + 32 * m;
#pragma unroll
        for (int x = 0; x < 8; ++x) buf[x] = V[t * 16 + c + x * 1024];
        fft8p<0>(buf);
#pragma unroll
        for (int x = 0; x < 8; ++x) og[(long)(x * 64 + t) * 2048] = buf[x];
    }
}

// ---------------------------------------------------------------------------
// Kernel 2: Hermitian pointwise complex GEMM, 260 canonical freqs, 512 thr.
// Tile 2(b) x 4(f). P/Q accumulation: P = sum ax*(bx,by), Q = sum ay*(bx,by);
// Y = (P.lo - Q.hi, P.hi + Q.lo). B loads are raw LDS.64, no packing movs.
// ---------------------------------------------------------------------------
__global__ void __launch_bounds__(512)
pointwise_kernel(float2* __restrict__ Zh) {
    const int rank = blockIdx.x;
    int kx, ky, kz;
    if (rank < 192) {
        kx = 1 + rank / 64; const int r = rank & 63; ky = r >> 3; kz = r & 7;
    } else if (rank < 240) {
        const int r = rank - 192; kx = (r / 24) * 4;
        const int r2 = r % 24; ky = 1 + r2 / 8; kz = r2 & 7;
    } else {
        const int r = rank - 240; kx = (r / 10) * 4;
        const int r2 = r % 10; ky = (r2 / 5) * 4; kz = r2 % 5;
    }
    const int k = (kx << 6) | (ky << 3) | kz;
    const int neg = (((8 - kx) & 7) << 6) | (((8 - ky) & 7) << 3) | ((8 - kz) & 7);

    extern __shared__ float2 sm[];
    float2* As = sm;            // [c][b], stride 65
    float2* Bs = sm + 64 * 65;  // [c][f], stride 65
    const int tid = threadIdx.x;

    const float2* xk = (const float2*)g_Xp + (long)k * 2048;
    const float2* xn = (const float2*)g_Xp + (long)neg * 2048;
    const float2* wk = (const float2*)g_Wp + (long)k * 2048;
    const float2* wn = (const float2*)g_Wp + (long)neg * 2048;
    for (int i = tid; i < 2048; i += 512) {
        const int j = i & 31, rowi = i >> 5;
        const int c0 = 2 * j, c1 = 2 * j + 1;
        {
            const float2 Pk = xk[i], Pn = xn[i];
            As[c0 * 65 + rowi] = make_float2(0.5f * (Pk.x + Pn.x), 0.5f * (Pk.y - Pn.y));
            As[c1 * 65 + rowi] = make_float2(0.5f * (Pk.y + Pn.y), 0.5f * (Pn.x - Pk.x));
        }
        {
            const float2 Pk = wk[i], Pn = wn[i];
            Bs[c0 * 65 + rowi] = make_float2(0.5f * (Pk.x + Pn.x), 0.5f * (Pk.y - Pn.y));
            Bs[c1 * 65 + rowi] = make_float2(0.5f * (Pk.y + Pn.y), 0.5f * (Pn.x - Pk.x));
        }
    }
    __syncthreads();

    const int ft = tid & 15;   // f = ft + 16j
    const int bt = tid >> 4;   // b = bt + 32i, bt in 0..31
    ull accP[2][4], accQ[2][4];
#pragma unroll
    for (int i = 0; i < 2; ++i)
#pragma unroll
        for (int j = 0; j < 4; ++j) { accP[i][j] = 0ULL; accQ[i][j] = 0ULL; }

    ull axx[2], ayy[2], bv[4];
#pragma unroll 4
    for (int cc = 0; cc < 64; ++cc) {
#pragma unroll
        for (int i = 0; i < 2; ++i) {
            const float2 t = As[cc * 65 + bt + 32 * i];
            axx[i] = pk(t.x, t.x);
            ayy[i] = pk(t.y, t.y);
        }
#pragma unroll
        for (int j = 0; j < 4; ++j)
            bv[j] = *(const ull*)&Bs[cc * 65 + ft + 16 * j];  // (bx, by) raw
#pragma unroll
        for (int i = 0; i < 2; ++i)
#pragma unroll
            for (int j = 0; j < 4; ++j) {
                accP[i][j] = fma2(axx[i], bv[j], accP[i][j]);  // (ax*bx, ax*by)
                accQ[i][j] = fma2(ayy[i], bv[j], accQ[i][j]);  // (ay*bx, ay*by)
            }
    }

    // Fixup + drain: Y = (P.lo - Q.hi, P.hi + Q.lo); pack f-pairs via shfl.
    float2* zk = Zh + (long)k * 2048;
    float2* zn = Zh + (long)neg * 2048;
    const bool self = (k == neg);
    const bool even = (ft & 1) == 0;
    const int fp0 = ft >> 1;
#pragma unroll
    for (int i = 0; i < 2; ++i)
#pragma unroll
        for (int j = 0; j < 4; ++j) {
            float px, py, qx, qy;
            upk(accP[i][j], px, py);
            upk(accQ[i][j], qx, qy);
            const ull y = pk(px - qy, py + qx);  // (Y.re, Y.im)
            const ull part = __shfl_xor_sync(0xffffffffu, y, 1);
            if (even) {
                float y0x, y0y, y1x, y1y;
                upk(y, y0x, y0y);      // f = 2fp
                upk(part, y1x, y1y);   // f = 2fp+1
                const int idx = (bt + 32 * i) * 32 + fp0 + 8 * j;
                zk[idx] = make_float2(y0x - y1y, y0y + y1x);
                if (!self) zn[idx] = make_float2(y0x + y1y, y1x - y0y);
            }
        }
}

// ---------------------------------------------------------------------------
// Kernel 3: inverse packed FFT + bias, 16-column tiles, 256 threads, grid 128.
// IFFT(Y_{2f}+iY_{2f+1}) = out_{2f} + i out_{2f+1}.
// ---------------------------------------------------------------------------
__global__ void __launch_bounds__(256)
ifft3d_packed(const ull* __restrict__ Zh, const float* __restrict__ bias,
              float* __restrict__ out) {
    extern __shared__ ull V[];
    const int b = blockIdx.x >> 1, fp0 = (blockIdx.x & 1) * 16;
    const int tid = threadIdx.x;
    const int c = tid & 15, pp = tid >> 4;
    const float2 bv = ((const float2*)bias)[fp0 + c];

    const ull* yg = Zh + b * 32 + fp0 + c;
    ull buf[8];

#pragma unroll
    for (int m = 0; m < 4; ++m) {  // z-axis + load
        const int t = pp + 16 * m;
#pragma unroll
        for (int z = 0; z < 8; ++z) buf[z] = yg[(long)(8 * t + z) * 2048];
        fft8p<1>(buf);
#pragma unroll
        for (int z = 0; z < 8; ++z) V[(8 * t + z) * 16 + c] = buf[z];
    }
    __syncthreads();
#pragma unroll
    for (int m = 0; m < 4; ++m) {  // y-axis
        const int t = pp + 16 * m;
        const int b0 = ((t >> 3) * 64 + (t & 7)) * 16 + c;
#pragma unroll
        for (int y = 0; y < 8; ++y) buf[y] = V[b0 + y * 128];
        fft8p<1>(buf);
#pragma unroll
        for (int y = 0; y < 8; ++y) V[b0 + y * 128] = buf[y];
    }
    __syncthreads();
    float2* og = (float2*)out + (long)b * 512 * 32 + fp0 + c;
#pragma unroll
    for (int m = 0; m < 4; ++m) {  // x-axis + store
        const int t = pp + 16 * m;
#pragma unroll
        for (int x = 0; x < 8; ++x) buf[x] = V[t * 16 + c + x * 1024];
        fft8p<1>(buf);
#pragma unroll
        for (int x = 0; x < 8; ++x) {
            float re, im;
            upk(buf[x], re, im);
            og[(long)(x * 64 + t) * 32] =
                make_float2(re * (1.f / 512.f) + bv.x, im * (1.f / 512.f) + bv.y);
        }
    }
}

// ---------------------------------------------------------------------------
extern "C" void kernel_launch(void* const* d_in, const int* in_sizes, int n_in,
                              void* d_out, int out_size) {
    const float* inputs = (const float*)d_in[0];
    const float* kern   = (const float*)d_in[1];
    const float* bias   = (const float*)d_in[2];
    float* out = (float*)d_out;

    ull *Xp, *Wp, *Zh;
    cudaGetSymbolAddress((void**)&Xp, g_Xp);
    cudaGetSymbolAddress((void**)&Wp, g_Wp);
    cudaGetSymbolAddress((void**)&Zh, g_Z);

    const int smemFFT = 512 * 16 * (int)sizeof(ull);       // 65536 B
    const int smemPW  = 2 * 64 * 65 * (int)sizeof(float2); // 66560 B
    cudaFuncSetAttribute(fft3d_fwd_packed, cudaFuncAttributeMaxDynamicSharedMemorySize, smemFFT);
    cudaFuncSetAttribute(ifft3d_packed,    cudaFuncAttributeMaxDynamicSharedMemorySize, smemFFT);
    cudaFuncSetAttribute(pointwise_kernel, cudaFuncAttributeMaxDynamicSharedMemorySize, smemPW);

    fft3d_fwd_packed<<<256, 512, smemFFT>>>(inputs, kern, Xp, Wp);
    pointwise_kernel<<<260, 512, smemPW>>>((float2*)Zh);
    ifft3d_packed<<<128, 256, smemFFT>>>(Zh, bias, out);
}

// round 15
// speedup vs baseline: 1.2281x; 1.0698x over previous
#include <cuda_runtime.h>

// ============================================================================
// TorusConv3D via FFT diagonalization (round 15).
// Round-15: MLP pass. fwd phase-1 loads all 16 global points (both m-iters)
// before any butterfly (regs 32 -> ~60, MLP 8 -> 16, hides L2/DRAM latency).
// ifft widened to 512 threads with the same batched phase-1 loads.
// Pointwise (round-14 P/Q winner) untouched.
// ============================================================================

typedef unsigned long long ull;

// Packed spectra: g_Xp[k*2048 + b*32 + j], g_Wp[k*2048 + f*32 + j],
//                 g_Z [k*2048 + b*32 + fp]
__device__ ull g_Xp[512 * 2048];
__device__ ull g_Wp[512 * 2048];
__device__ ull g_Z[512 * 2048];

// ---------------------------------------------------------------------------
// Packed f32x2 primitives. A complex value is (re, im) = (lo, hi) of an ull.
// ---------------------------------------------------------------------------
__device__ __forceinline__ ull pk(float lo, float hi) {
    ull r;
    asm("mov.b64 %0, {%1, %2};" : "=l"(r) : "f"(lo), "f"(hi));
    return r;
}
__device__ __forceinline__ void upk(ull v, float& lo, float& hi) {
    asm("mov.b64 {%0, %1}, %2;" : "=f"(lo), "=f"(hi) : "l"(v));
}
__device__ __forceinline__ ull add2(ull a, ull b) {
    ull d;
    asm("add.rn.f32x2 %0, %1, %2;" : "=l"(d) : "l"(a), "l"(b));
    return d;
}
__device__ __forceinline__ ull mul2(ull a, ull b) {
    ull d;
    asm("mul.rn.f32x2 %0, %1, %2;" : "=l"(d) : "l"(a), "l"(b));
    return d;
}
__device__ __forceinline__ ull fma2(ull a, ull b, ull c) {
    ull d;
    asm("fma.rn.f32x2 %0, %1, %2, %3;" : "=l"(d) : "l"(a), "l"(b), "l"(c));
    return d;
}
__device__ __forceinline__ ull sub2(ull a, ull b) {
    return fma2(b, 0xBF800000BF800000ULL, a);  // a + (-1)*b
}
__device__ __forceinline__ float negf(float x) {
    return __uint_as_float(__float_as_uint(x) ^ 0x80000000u);
}
template <int INV>
__device__ __forceinline__ ull mi(ull a) {  // *(-i) fwd, *(+i) inv
    float x, y;
    upk(a, x, y);
    return INV ? pk(negf(y), x) : pk(y, negf(x));
}

#define R2R2 0x3F3504F33F3504F3ULL  // (sqrt(0.5), sqrt(0.5))

template <int INV>
__device__ __forceinline__ void fft8p(ull* v) {
    ull t0 = add2(v[0], v[4]), t1 = sub2(v[0], v[4]);
    ull t2 = add2(v[2], v[6]), t3 = sub2(v[2], v[6]);
    ull t4 = add2(v[1], v[5]), t5 = sub2(v[1], v[5]);
    ull t6 = add2(v[3], v[7]), t7 = sub2(v[3], v[7]);
    ull a0 = add2(t0, t2), a1 = sub2(t0, t2);
    ull m3 = mi<INV>(t3);
    ull a2 = add2(t1, m3), a3 = sub2(t1, m3);
    ull b0 = add2(t4, t6), b1 = sub2(t4, t6);
    ull m7 = mi<INV>(t7);
    ull b2 = add2(t5, m7), b3 = sub2(t5, m7);
    ull mb1 = mi<INV>(b1);
    ull w1v = mul2(add2(b2, mi<INV>(b2)), R2R2);
    ull w3v = mi<INV>(mul2(add2(b3, mi<INV>(b3)), R2R2));
    v[0] = add2(a0, b0); v[4] = sub2(a0, b0);
    v[2] = add2(a1, mb1); v[6] = sub2(a1, mb1);
    v[1] = add2(a2, w1v); v[5] = sub2(a2, w1v);
    v[3] = add2(a3, w3v); v[7] = sub2(a3, w3v);
}

// ---------------------------------------------------------------------------
// Kernel 1: forward packed FFT, 16-column tiles, 512 threads.
// Phase 1 loads BOTH m-iterations (16 points) before any compute (MLP=16).
// Blocks [0,128) -> inputs->Xp, [128,256) -> kernel->Wp.
// ---------------------------------------------------------------------------
__global__ void __launch_bounds__(512)
fft3d_fwd_packed(const float* __restrict__ inA, const float* __restrict__ inB,
                 ull* __restrict__ outA, ull* __restrict__ outB) {
    extern __shared__ ull V[];
    int blk = blockIdx.x;
    const float* in;
    ull* out;
    long rowStride, sStride;
    if (blk < 128) { in = inA; out = outA; rowStride = 32768; sStride = 64; }
    else           { blk -= 128; in = inB; out = outB; rowStride = 64; sStride = 4096; }
    const int row = blk >> 1, j0 = (blk & 1) * 16;
    const int tid = threadIdx.x;
    const int c = tid & 15, pp = tid >> 4;

    const float* base = in + (long)row * rowStride + 2 * (j0 + c);

    // Phase 1: batched load of 16 points (t = pp and pp+32), then 2 FFTs + STS.
    ull d[16];
#pragma unroll
    for (int m = 0; m < 2; ++m) {
        const int t = pp + 32 * m;
#pragma unroll
        for (int z = 0; z < 8; ++z)
            d[m * 8 + z] = *(const ull*)(base + (long)(8 * t + z) * sStride);
    }
#pragma unroll
    for (int m = 0; m < 2; ++m) {
        const int t = pp + 32 * m;
        fft8p<0>(d + m * 8);
#pragma unroll
        for (int z = 0; z < 8; ++z) V[(8 * t + z) * 16 + c] = d[m * 8 + z];
    }
    __syncthreads();

    // Phase 2: y-axis through smem. t = (x,z). stride 128.
    ull buf[8];
#pragma unroll
    for (int m = 0; m < 2; ++m) {
        const int t = pp + 32 * m;
        const int b0 = ((t >> 3) * 64 + (t & 7)) * 16 + c;
#pragma unroll
        for (int y = 0; y < 8; ++y) buf[y] = V[b0 + y * 128];
        fft8p<0>(buf);
#pragma unroll
        for (int y = 0; y < 8; ++y) V[b0 + y * 128] = buf[y];
    }
    __syncthreads();

    // Phase 3: x-axis fused with global store. t = (ky,kz). stride 1024.
    ull* og = out + row * 32 + j0 + c;
#pragma unroll
    for (int m = 0; m < 2; ++m) {
        const int t = pp + 32 * m;
#pragma unroll
        for (int x = 0; x < 8; ++x) buf[x] = V[t * 16 + c + x * 1024];
        fft8p<0>(buf);
#pragma unroll
        for (int x = 0; x < 8; ++x) og[(long)(x * 64 + t) * 2048] = buf[x];
    }
}

// ---------------------------------------------------------------------------
// Kernel 2: Hermitian pointwise complex GEMM (round-14 winner, unchanged).
// 260 canonical freqs, 512 threads, 2(b) x 4(f) tiles, P/Q accumulation.
// ---------------------------------------------------------------------------
__global__ void __launch_bounds__(512)
pointwise_kernel(float2* __restrict__ Zh) {
    const int rank = blockIdx.x;
    int kx, ky, kz;
    if (rank < 192) {
        kx = 1 + rank / 64; const int r = rank & 63; ky = r >> 3; kz = r & 7;
    } else if (rank < 240) {
        const int r = rank - 192; kx = (r / 24) * 4;
        const int r2 = r % 24; ky = 1 + r2 / 8; kz = r2 & 7;
    } else {
        const int r = rank - 240; kx = (r / 10) * 4;
        const int r2 = r % 10; ky = (r2 / 5) * 4; kz = r2 % 5;
    }
    const int k = (kx << 6) | (ky << 3) | kz;
    const int neg = (((8 - kx) & 7) << 6) | (((8 - ky) & 7) << 3) | ((8 - kz) & 7);

    extern __shared__ float2 sm[];
    float2* As = sm;            // [c][b], stride 65
    float2* Bs = sm + 64 * 65;  // [c][f], stride 65
    const int tid = threadIdx.x;

    const float2* xk = (const float2*)g_Xp + (long)k * 2048;
    const float2* xn = (const float2*)g_Xp + (long)neg * 2048;
    const float2* wk = (const float2*)g_Wp + (long)k * 2048;
    const float2* wn = (const float2*)g_Wp + (long)neg * 2048;
    for (int i = tid; i < 2048; i += 512) {
        const int j = i & 31, rowi = i >> 5;
        const int c0 = 2 * j, c1 = 2 * j + 1;
        {
            const float2 Pk = xk[i], Pn = xn[i];
            As[c0 * 65 + rowi] = make_float2(0.5f * (Pk.x + Pn.x), 0.5f * (Pk.y - Pn.y));
            As[c1 * 65 + rowi] = make_float2(0.5f * (Pk.y + Pn.y), 0.5f * (Pn.x - Pk.x));
        }
        {
            const float2 Pk = wk[i], Pn = wn[i];
            Bs[c0 * 65 + rowi] = make_float2(0.5f * (Pk.x + Pn.x), 0.5f * (Pk.y - Pn.y));
            Bs[c1 * 65 + rowi] = make_float2(0.5f * (Pk.y + Pn.y), 0.5f * (Pn.x - Pk.x));
        }
    }
    __syncthreads();

    const int ft = tid & 15;   // f = ft + 16j
    const int bt = tid >> 4;   // b = bt + 32i
    ull accP[2][4], accQ[2][4];
#pragma unroll
    for (int i = 0; i < 2; ++i)
#pragma unroll
        for (int j = 0; j < 4; ++j) { accP[i][j] = 0ULL; accQ[i][j] = 0ULL; }

    ull axx[2], ayy[2], bv[4];
#pragma unroll 4
    for (int cc = 0; cc < 64; ++cc) {
#pragma unroll
        for (int i = 0; i < 2; ++i) {
            const float2 t = As[cc * 65 + bt + 32 * i];
            axx[i] = pk(t.x, t.x);
            ayy[i] = pk(t.y, t.y);
        }
#pragma unroll
        for (int j = 0; j < 4; ++j)
            bv[j] = *(const ull*)&Bs[cc * 65 + ft + 16 * j];  // (bx, by) raw
#pragma unroll
        for (int i = 0; i < 2; ++i)
#pragma unroll
            for (int j = 0; j < 4; ++j) {
                accP[i][j] = fma2(axx[i], bv[j], accP[i][j]);  // (ax*bx, ax*by)
                accQ[i][j] = fma2(ayy[i], bv[j], accQ[i][j]);  // (ay*bx, ay*by)
            }
    }

    // Fixup + drain: Y = (P.lo - Q.hi, P.hi + Q.lo); pack f-pairs via shfl.
    float2* zk = Zh + (long)k * 2048;
    float2* zn = Zh + (long)neg * 2048;
    const bool self = (k == neg);
    const bool even = (ft & 1) == 0;
    const int fp0 = ft >> 1;
#pragma unroll
    for (int i = 0; i < 2; ++i)
#pragma unroll
        for (int j = 0; j < 4; ++j) {
            float px, py, qx, qy;
            upk(accP[i][j], px, py);
            upk(accQ[i][j], qx, qy);
            const ull y = pk(px - qy, py + qx);  // (Y.re, Y.im)
            const ull part = __shfl_xor_sync(0xffffffffu, y, 1);
            if (even) {
                float y0x, y0y, y1x, y1y;
                upk(y, y0x, y0y);      // f = 2fp
                upk(part, y1x, y1y);   // f = 2fp+1
                const int idx = (bt + 32 * i) * 32 + fp0 + 8 * j;
                zk[idx] = make_float2(y0x - y1y, y0y + y1x);
                if (!self) zn[idx] = make_float2(y0x + y1y, y1x - y0y);
            }
        }
}

// ---------------------------------------------------------------------------
// Kernel 3: inverse packed FFT + bias, 16-column tiles, 512 threads, grid 128.
// Phase 1 loads both m-iterations (16 points of Z) before compute.
// IFFT(Y_{2f}+iY_{2f+1}) = out_{2f} + i out_{2f+1}.
// ---------------------------------------------------------------------------
__global__ void __launch_bounds__(512)
ifft3d_packed(const ull* __restrict__ Zh, const float* __restrict__ bias,
              float* __restrict__ out) {
    extern __shared__ ull V[];
    const int b = blockIdx.x >> 1, fp0 = (blockIdx.x & 1) * 16;
    const int tid = threadIdx.x;
    const int c = tid & 15, pp = tid >> 4;
    const float2 bv = ((const float2*)bias)[fp0 + c];

    const ull* yg = Zh + b * 32 + fp0 + c;

    // Phase 1: batched load (16 points), then 2 FFTs + STS.
    ull d[16];
#pragma unroll
    for (int m = 0; m < 2; ++m) {
        const int t = pp + 32 * m;
#pragma unroll
        for (int z = 0; z < 8; ++z)
            d[m * 8 + z] = yg[(long)(8 * t + z) * 2048];
    }
#pragma unroll
    for (int m = 0; m < 2; ++m) {
        const int t = pp + 32 * m;
        fft8p<1>(d + m * 8);
#pragma unroll
        for (int z = 0; z < 8; ++z) V[(8 * t + z) * 16 + c] = d[m * 8 + z];
    }
    __syncthreads();

    // Phase 2: y-axis.
    ull buf[8];
#pragma unroll
    for (int m = 0; m < 2; ++m) {
        const int t = pp + 32 * m;
        const int b0 = ((t >> 3) * 64 + (t & 7)) * 16 + c;
#pragma unroll
        for (int y = 0; y < 8; ++y) buf[y] = V[b0 + y * 128];
        fft8p<1>(buf);
#pragma unroll
        for (int y = 0; y < 8; ++y) V[b0 + y * 128] = buf[y];
    }
    __syncthreads();

    // Phase 3: x-axis fused with store (re -> 2fp, im -> 2fp+1, +bias).
    float2* og = (float2*)out + (long)b * 512 * 32 + fp0 + c;
#pragma unroll
    for (int m = 0; m < 2; ++m) {
        const int t = pp + 32 * m;
#pragma unroll
        for (int x = 0; x < 8; ++x) buf[x] = V[t * 16 + c + x * 1024];
        fft8p<1>(buf);
#pragma unroll
        for (int x = 0; x < 8; ++x) {
            float re, im;
            upk(buf[x], re, im);
            og[(long)(x * 64 + t) * 32] =
                make_float2(re * (1.f / 512.f) + bv.x, im * (1.f / 512.f) + bv.y);
        }
    }
}

// ---------------------------------------------------------------------------
extern "C" void kernel_launch(void* const* d_in, const int* in_sizes, int n_in,
                              void* d_out, int out_size) {
    const float* inputs = (const float*)d_in[0];
    const float* kern   = (const float*)d_in[1];
    const float* bias   = (const float*)d_in[2];
    float* out = (float*)d_out;

    ull *Xp, *Wp, *Zh;
    cudaGetSymbolAddress((void**)&Xp, g_Xp);
    cudaGetSymbolAddress((void**)&Wp, g_Wp);
    cudaGetSymbolAddress((void**)&Zh, g_Z);

    const int smemFFT = 512 * 16 * (int)sizeof(ull);       // 65536 B
    const int smemPW  = 2 * 64 * 65 * (int)sizeof(float2); // 66560 B
    cudaFuncSetAttribute(fft3d_fwd_packed, cudaFuncAttributeMaxDynamicSharedMemorySize, smemFFT);
    cudaFuncSetAttribute(ifft3d_packed,    cudaFuncAttributeMaxDynamicSharedMemorySize, smemFFT);
    cudaFuncSetAttribute(pointwise_kernel, cudaFuncAttributeMaxDynamicSharedMemorySize, smemPW);

    fft3d_fwd_packed<<<256, 512, smemFFT>>>(inputs, kern, Xp, Wp);
    pointwise_kernel<<<260, 512, smemPW>>>((float2*)Zh);
    ifft3d_packed<<<128, 512, smemFFT>>>(Zh, bias, out);
}